// round 15
// baseline (speedup 1.0000x reference)
#include <cuda_runtime.h>
#include <cuda_fp16.h>

#define N_NODES  200000
#define N_EDGES  6400000
#define N_GRAPHS 512
#define STRIDE   64          // CSR bucket capacity (mean deg 32, sigma 5.7; 5.7σ tail safe)

// Packed dual fp32 FMA (sm_103a): acc = w * h + acc on both lanes.
#define FMA2(acc, w, hh) \
    asm("fma.rn.f32x2 %0, %1, %2, %0;" : "+l"(acc) : "l"(w), "l"(hh))
#define UNPACK2(lo, hi, acc) \
    asm("mov.b64 {%0, %1}, %2;" : "=r"(lo), "=r"(hi) : "l"(acc))

// Vectorized fire-and-forget global reduction (sm_90+)
__device__ __forceinline__ void red4(float* a, float4 v) {
    asm volatile("red.global.add.v4.f32 [%0], {%1,%2,%3,%4};"
                 :: "l"(a), "f"(v.x), "f"(v.y), "f"(v.z), "f"(v.w)
                 : "memory");
}

// ---------------- scratch (device globals; no allocation allowed) ----------
__device__ int   g_flag64;                   // 1 if indices are int64
__device__ int   g_cnt[N_NODES];             // per-node in-degree (atomic cursor)
__device__ __align__(256) int    g_csr [N_NODES * STRIDE];  // 51.2MB bucketed CSR
__device__ __align__(256) float4 g_x4  [N_NODES];           // x padded to 16B rows
__device__ __align__(256) float  g_agg1[N_NODES * 4];
__device__ __align__(256) __half g_t2h [N_NODES * 16];      // h1 @ W2_rel^T (fp16)
__device__ __align__(256) float  g_r2  [N_NODES * 16];      // h1 @ W2_root^T
__device__ __align__(256) float  g_agg2[N_NODES * 16];
__device__ __align__(256) __half g_t3h [N_NODES * 8];       // h2 @ W3_rel^T (fp16)
__device__ __align__(256) float  g_r3  [N_NODES * 8];
__device__ __align__(256) float  g_agg3[N_NODES * 8];
__device__ __align__(256) float  g_pool[N_GRAPHS * 8];

// ---------------- zero + pad x + dtype probe (block 0) ---------------------
__global__ void k_zero(const float* __restrict__ x, const int* __restrict__ ei32) {
    int i = blockIdx.x * blockDim.x + threadIdx.x;
    if (i < N_NODES) {
        g_cnt[i] = 0;
        const float* xp = x + (long long)i * 3;
        g_x4[i] = make_float4(xp[0], xp[1], xp[2], 0.f);
        *reinterpret_cast<float4*>(g_agg1 + i * 4) = make_float4(0.f, 0.f, 0.f, 0.f);
    }
    if (i < N_GRAPHS * 8) g_pool[i] = 0.f;
    if (blockIdx.x == 0) {
        int nz = 0;
#pragma unroll
        for (int j = 0; j < 8; j++) nz += (ei32[1 + 2 * (threadIdx.x * 8 + j)] != 0);
        int total = __syncthreads_count(nz != 0);
        if (threadIdx.x == 0) g_flag64 = (total == 0) ? 1 : 0;
    }
}

// ---- single edge pass: bucketed CSR placement + layer-1 push aggregation ---
__global__ void k_place(const void* __restrict__ ei) {
    int t = blockIdx.x * blockDim.x + threadIdx.x;
    int e = t * 4;                       // grid sized exactly: no bounds check
    long long s[4], d[4];
    if (g_flag64) {
        const long long* p = reinterpret_cast<const long long*>(ei);
        longlong2 a0 = *reinterpret_cast<const longlong2*>(p + e);
        longlong2 a1 = *reinterpret_cast<const longlong2*>(p + e + 2);
        longlong2 b0 = *reinterpret_cast<const longlong2*>(p + N_EDGES + e);
        longlong2 b1 = *reinterpret_cast<const longlong2*>(p + N_EDGES + e + 2);
        s[0] = a0.x; s[1] = a0.y; s[2] = a1.x; s[3] = a1.y;
        d[0] = b0.x; d[1] = b0.y; d[2] = b1.x; d[3] = b1.y;
    } else {
        const int* p = reinterpret_cast<const int*>(ei);
        int4 a = *reinterpret_cast<const int4*>(p + e);
        int4 b = *reinterpret_cast<const int4*>(p + N_EDGES + e);
        s[0] = a.x; s[1] = a.y; s[2] = a.z; s[3] = a.w;
        d[0] = b.x; d[1] = b.y; d[2] = b.z; d[3] = b.w;
    }
#pragma unroll
    for (int u = 0; u < 4; u++) {
        int p = atomicAdd(&g_cnt[d[u]], 1);
        if (p < STRIDE) g_csr[d[u] * STRIDE + p] = (int)s[u];
    }
#pragma unroll
    for (int u = 0; u < 4; u++) {
        float4 v = __ldg(&g_x4[s[u]]);   // w component is 0
        red4(g_agg1 + d[u] * 4, v);
    }
}

// ---------------- pull aggregation, layer 2 (16 halfs, fp32 accum) ----------
__global__ void k_agg2() {
    int gid = blockIdx.x * blockDim.x + threadIdx.x;
    int node = gid >> 2, sub = gid & 3;
    int deg = min(g_cnt[node], STRIDE);
    int base = node * STRIDE;
    const int4* cp = reinterpret_cast<const int4*>(g_csr + base);
    const uint2* t2 = reinterpret_cast<const uint2*>(g_t2h);  // 4 halfs per uint2
    float4 acc = make_float4(0.f, 0.f, 0.f, 0.f);
    int k4 = deg >> 2;
#pragma unroll 2
    for (int q = 0; q < k4; q++) {
        int4 s = __ldg(cp + q);
        uint2 a = __ldg(t2 + (size_t)s.x * 4 + sub);
        uint2 b = __ldg(t2 + (size_t)s.y * 4 + sub);
        uint2 c = __ldg(t2 + (size_t)s.z * 4 + sub);
        uint2 d = __ldg(t2 + (size_t)s.w * 4 + sub);
#pragma unroll
        for (int r = 0; r < 4; r++) {
            uint2 v = (r == 0) ? a : (r == 1) ? b : (r == 2) ? c : d;
            float2 f0 = __half22float2(*reinterpret_cast<__half2*>(&v.x));
            float2 f1 = __half22float2(*reinterpret_cast<__half2*>(&v.y));
            acc.x += f0.x; acc.y += f0.y; acc.z += f1.x; acc.w += f1.y;
        }
    }
    for (int k = k4 * 4; k < deg; k++) {
        int s = __ldg(&g_csr[base + k]);
        uint2 v = __ldg(t2 + (size_t)s * 4 + sub);
        float2 f0 = __half22float2(*reinterpret_cast<__half2*>(&v.x));
        float2 f1 = __half22float2(*reinterpret_cast<__half2*>(&v.y));
        acc.x += f0.x; acc.y += f0.y; acc.z += f1.x; acc.w += f1.y;
    }
    reinterpret_cast<float4*>(g_agg2)[(size_t)node * 4 + sub] = acc;
}

// ---------------- pull aggregation, layer 3 (8 halfs, fp32 accum) -----------
__global__ void k_agg3() {
    int gid = blockIdx.x * blockDim.x + threadIdx.x;
    int node = gid >> 2, sub = gid & 3;
    int deg = min(g_cnt[node], STRIDE);
    int base = node * STRIDE;
    const int4* cp = reinterpret_cast<const int4*>(g_csr + base);
    const unsigned* t3 = reinterpret_cast<const unsigned*>(g_t3h);  // 2 halfs per uint
    float2 acc = make_float2(0.f, 0.f);
    int k4 = deg >> 2;
#pragma unroll 2
    for (int q = 0; q < k4; q++) {
        int4 s = __ldg(cp + q);
        unsigned a = __ldg(t3 + (size_t)s.x * 4 + sub);
        unsigned b = __ldg(t3 + (size_t)s.y * 4 + sub);
        unsigned c = __ldg(t3 + (size_t)s.z * 4 + sub);
        unsigned d = __ldg(t3 + (size_t)s.w * 4 + sub);
        float2 fa = __half22float2(*reinterpret_cast<__half2*>(&a));
        float2 fb = __half22float2(*reinterpret_cast<__half2*>(&b));
        float2 fc = __half22float2(*reinterpret_cast<__half2*>(&c));
        float2 fd = __half22float2(*reinterpret_cast<__half2*>(&d));
        acc.x += (fa.x + fb.x) + (fc.x + fd.x);
        acc.y += (fa.y + fb.y) + (fc.y + fd.y);
    }
    for (int k = k4 * 4; k < deg; k++) {
        int s = __ldg(&g_csr[base + k]);
        unsigned v = __ldg(t3 + (size_t)s * 4 + sub);
        float2 f = __half22float2(*reinterpret_cast<__half2*>(&v));
        acc.x += f.x; acc.y += f.y;
    }
    reinterpret_cast<float2*>(g_agg3)[(size_t)node * 4 + sub] = acc;
}

// ---------------- node pass 1: h1 = relu(...); t2/r2 = h1 @ W2^T ------------
// ONE thread per node, broadcast weight LDS (96 regs, pareto-optimal).
__global__ void k_node1(const float* __restrict__ W1_rel, const float* __restrict__ b1,
                        const float* __restrict__ W1_root,
                        const float* __restrict__ W2_rel, const float* __restrict__ W2_root) {
    __shared__ float4 s1rel[32];    // (w0,w1,w2,bias)
    __shared__ float4 s1root[32];   // (w0,w1,w2,0)
    __shared__ float4 s2rel[128];   // 16x32 natural row-major
    __shared__ float4 s2root[128];
    if (threadIdx.x < 32) {
        int o = threadIdx.x;
        s1rel[o]  = make_float4(W1_rel[o * 3], W1_rel[o * 3 + 1], W1_rel[o * 3 + 2], b1[o]);
        s1root[o] = make_float4(W1_root[o * 3], W1_root[o * 3 + 1], W1_root[o * 3 + 2], 0.f);
    }
    for (int j = threadIdx.x; j < 128; j += blockDim.x) {
        s2rel[j]  = reinterpret_cast<const float4*>(W2_rel)[j];
        s2root[j] = reinterpret_cast<const float4*>(W2_root)[j];
    }
    __syncthreads();

    int i = blockIdx.x * blockDim.x + threadIdx.x;
    if (i >= N_NODES) return;

    float4 a  = *reinterpret_cast<const float4*>(g_agg1 + i * 4);
    float4 xv = __ldg(&g_x4[i]);

    // h1 packed as consecutive-k pairs: hh[kk] = {h[2kk], h[2kk+1]}
    unsigned long long hh[16];
#pragma unroll
    for (int kk = 0; kk < 16; kk++) {
        unsigned u[2];
#pragma unroll
        for (int half = 0; half < 2; half++) {
            int o = kk * 2 + half;
            float4 wa = s1rel[o];
            float4 wr = s1root[o];
            float v = wa.w;
            v = fmaf(wa.x, a.x, v);  v = fmaf(wa.y, a.y, v);  v = fmaf(wa.z, a.z, v);
            v = fmaf(wr.x, xv.x, v); v = fmaf(wr.y, xv.y, v); v = fmaf(wr.z, xv.z, v);
            u[half] = __float_as_uint(fmaxf(v, 0.f));
        }
        asm("mov.b64 %0, {%1, %2};" : "=l"(hh[kk]) : "r"(u[0]), "r"(u[1]));
    }

    const ulonglong2* wrel  = reinterpret_cast<const ulonglong2*>(s2rel);
    const ulonglong2* wroot = reinterpret_cast<const ulonglong2*>(s2root);

    // t2 outputs: 16 rows (fp16)
    __half2 hp[8];
#pragma unroll
    for (int p = 0; p < 8; p++) {
        float res[2];
#pragma unroll
        for (int half = 0; half < 2; half++) {
            int o = p * 2 + half;
            unsigned long long acc = 0ULL;
#pragma unroll
            for (int c = 0; c < 8; c++) {           // c = 4-k chunk
                ulonglong2 w = wrel[o * 8 + c];
                FMA2(acc, w.x, hh[c * 2]);
                FMA2(acc, w.y, hh[c * 2 + 1]);
            }
            unsigned lo, hi; UNPACK2(lo, hi, acc);
            res[half] = __uint_as_float(lo) + __uint_as_float(hi);
        }
        hp[p] = __floats2half2_rn(res[0], res[1]);
    }
    uint4* tp = reinterpret_cast<uint4*>(g_t2h + (size_t)i * 16);
    tp[0] = *reinterpret_cast<uint4*>(hp);
    tp[1] = *reinterpret_cast<uint4*>(hp + 4);

    // r2 outputs: 16 rows (fp32)
    float rv[16];
#pragma unroll
    for (int o = 0; o < 16; o++) {
        unsigned long long acc = 0ULL;
#pragma unroll
        for (int c = 0; c < 8; c++) {
            ulonglong2 w = wroot[o * 8 + c];
            FMA2(acc, w.x, hh[c * 2]);
            FMA2(acc, w.y, hh[c * 2 + 1]);
        }
        unsigned lo, hi; UNPACK2(lo, hi, acc);
        rv[o] = __uint_as_float(lo) + __uint_as_float(hi);
    }
    float4* rp = reinterpret_cast<float4*>(g_r2 + (size_t)i * 16);
#pragma unroll
    for (int q = 0; q < 4; q++)
        rp[q] = make_float4(rv[q * 4], rv[q * 4 + 1], rv[q * 4 + 2], rv[q * 4 + 3]);
}

// ---------------- node pass 2: h2 = relu(agg2 + r2 + b2); t3(fp16)/r3 -------
__global__ void k_node2(const float* __restrict__ b2,
                        const float* __restrict__ W3_rel, const float* __restrict__ W3_root) {
    __shared__ float4 sb2[4];
    __shared__ float4 s3rel[32];    // 8 rows x 4 float4
    __shared__ float4 s3root[32];
    if (threadIdx.x < 4)  sb2[threadIdx.x] = reinterpret_cast<const float4*>(b2)[threadIdx.x];
    if (threadIdx.x >= 32 && threadIdx.x < 64)
        s3rel[threadIdx.x - 32] = reinterpret_cast<const float4*>(W3_rel)[threadIdx.x - 32];
    if (threadIdx.x >= 64 && threadIdx.x < 96)
        s3root[threadIdx.x - 64] = reinterpret_cast<const float4*>(W3_root)[threadIdx.x - 64];
    __syncthreads();

    int i = blockIdx.x * blockDim.x + threadIdx.x;
    if (i >= N_NODES) return;

    float h[16];
    const float4* ap = reinterpret_cast<const float4*>(g_agg2 + i * 16);
    const float4* rp = reinterpret_cast<const float4*>(g_r2 + i * 16);
#pragma unroll
    for (int q = 0; q < 4; q++) {
        float4 av = ap[q];
        float4 rv = rp[q];
        float4 bv = sb2[q];
        h[q * 4 + 0] = fmaxf(av.x + rv.x + bv.x, 0.f);
        h[q * 4 + 1] = fmaxf(av.y + rv.y + bv.y, 0.f);
        h[q * 4 + 2] = fmaxf(av.z + rv.z + bv.z, 0.f);
        h[q * 4 + 3] = fmaxf(av.w + rv.w + bv.w, 0.f);
    }

    float tv[8], rv2[8];
#pragma unroll
    for (int o = 0; o < 8; o++) {
        float tt = 0.f, rr = 0.f;
#pragma unroll
        for (int k = 0; k < 4; k++) {
            float4 wt = s3rel[o * 4 + k];
            float4 wr = s3root[o * 4 + k];
            tt = fmaf(h[k * 4 + 0], wt.x, tt); tt = fmaf(h[k * 4 + 1], wt.y, tt);
            tt = fmaf(h[k * 4 + 2], wt.z, tt); tt = fmaf(h[k * 4 + 3], wt.w, tt);
            rr = fmaf(h[k * 4 + 0], wr.x, rr); rr = fmaf(h[k * 4 + 1], wr.y, rr);
            rr = fmaf(h[k * 4 + 2], wr.z, rr); rr = fmaf(h[k * 4 + 3], wr.w, rr);
        }
        tv[o] = tt; rv2[o] = rr;
    }
    __half2 hp[4];
#pragma unroll
    for (int q = 0; q < 4; q++) hp[q] = __floats2half2_rn(tv[q * 2], tv[q * 2 + 1]);
    *reinterpret_cast<uint4*>(g_t3h + i * 8) = *reinterpret_cast<uint4*>(hp);

    float4* r3p = reinterpret_cast<float4*>(g_r3 + i * 8);
    r3p[0] = make_float4(rv2[0], rv2[1], rv2[2], rv2[3]);
    r3p[1] = make_float4(rv2[4], rv2[5], rv2[6], rv2[7]);
}

// ---------------- node pass 3: h3 = relu(agg3 + r3 + b3); segment max -------
__global__ void k_node3(const void* __restrict__ batch,
                        const float* __restrict__ b3) {
    int i = blockIdx.x * blockDim.x + threadIdx.x;
    if (i >= N_NODES) i = N_NODES - 1;  // duplicates harmless under max
    int lane = threadIdx.x & 31;

    float h[8];
    const float4* ap = reinterpret_cast<const float4*>(g_agg3 + i * 8);
    const float4* rp = reinterpret_cast<const float4*>(g_r3 + i * 8);
#pragma unroll
    for (int q = 0; q < 2; q++) {
        float4 av = ap[q];
        float4 rv = rp[q];
        h[q * 4 + 0] = fmaxf(av.x + rv.x + __ldg(b3 + q * 4 + 0), 0.f);
        h[q * 4 + 1] = fmaxf(av.y + rv.y + __ldg(b3 + q * 4 + 1), 0.f);
        h[q * 4 + 2] = fmaxf(av.z + rv.z + __ldg(b3 + q * 4 + 2), 0.f);
        h[q * 4 + 3] = fmaxf(av.w + rv.w + __ldg(b3 + q * 4 + 3), 0.f);
    }
    int b;
    if (g_flag64) b = (int)reinterpret_cast<const long long*>(batch)[i];
    else          b = reinterpret_cast<const int*>(batch)[i];

    const unsigned m = 0xffffffffu;
#pragma unroll
    for (int off = 1; off < 32; off <<= 1) {
        int ob = __shfl_down_sync(m, b, off);
#pragma unroll
        for (int d = 0; d < 8; d++) {
            float oh = __shfl_down_sync(m, h[d], off);
            if (ob == b) h[d] = fmaxf(h[d], oh);
        }
    }
    int pb = __shfl_up_sync(m, b, 1);
    bool leader = (lane == 0) || (pb != b);
    if (leader) {
#pragma unroll
        for (int d = 0; d < 8; d++)
            atomicMax(reinterpret_cast<int*>(&g_pool[b * 8 + d]), __float_as_int(h[d]));
    }
}

// ---------------- final: out[g] = pooled[g] . W_lin + b_lin -----------------
__global__ void k_final(const float* __restrict__ W_lin, const float* __restrict__ b_lin,
                        float* __restrict__ out) {
    int g = blockIdx.x * blockDim.x + threadIdx.x;
    if (g >= N_GRAPHS) return;
    float acc = __ldg(b_lin);
#pragma unroll
    for (int d = 0; d < 8; d++) acc += g_pool[g * 8 + d] * __ldg(W_lin + d);
    out[g] = acc;
}

// ---------------- launch ----------------------------------------------------
extern "C" void kernel_launch(void* const* d_in, const int* in_sizes, int n_in,
                              void* d_out, int out_size) {
    const float* x      = (const float*)d_in[0];
    const void*  ei     = d_in[1];
    const void*  batch  = d_in[2];
    const float* W1_rel = (const float*)d_in[3];
    const float* b1     = (const float*)d_in[4];
    const float* W1_root= (const float*)d_in[5];
    const float* W2_rel = (const float*)d_in[6];
    const float* b2     = (const float*)d_in[7];
    const float* W2_root= (const float*)d_in[8];
    const float* W3_rel = (const float*)d_in[9];
    const float* b3     = (const float*)d_in[10];
    const float* W3_root= (const float*)d_in[11];
    const float* W_lin  = (const float*)d_in[12];
    const float* b_lin  = (const float*)d_in[13];
    float* out = (float*)d_out;

    const int PLACE_BLOCKS = N_EDGES / 4 / 256;         // 6250 exact
    const int AGG_BLOCKS   = (N_NODES * 4) / 256;       // 3125 exact
    const int NODE_BLOCKS  = (N_NODES + 255) / 256;     // 782

    k_zero<<<NODE_BLOCKS, 256>>>(x, (const int*)ei);
    k_place<<<PLACE_BLOCKS, 256>>>(ei);
    k_node1<<<NODE_BLOCKS, 256>>>(W1_rel, b1, W1_root, W2_rel, W2_root);
    k_agg2<<<AGG_BLOCKS, 256>>>();
    k_node2<<<NODE_BLOCKS, 256>>>(b2, W3_rel, W3_root);
    k_agg3<<<AGG_BLOCKS, 256>>>();
    k_node3<<<NODE_BLOCKS, 256>>>(batch, b3);
    k_final<<<2, 256>>>(W_lin, b_lin, out);
}

// round 16
// speedup vs baseline: 1.0676x; 1.0676x over previous
#include <cuda_runtime.h>
#include <cuda_fp16.h>

#define N_NODES  200000
#define N_EDGES  6400000
#define N_GRAPHS 512
#define STRIDE   64          // CSR bucket capacity (mean deg 32, sigma 5.7; 5.7σ tail safe)

// Packed dual fp32 FMA (sm_103a): acc = w * h + acc on both lanes.
#define FMA2(acc, w, hh) \
    asm("fma.rn.f32x2 %0, %1, %2, %0;" : "+l"(acc) : "l"(w), "l"(hh))
#define UNPACK2(lo, hi, acc) \
    asm("mov.b64 {%0, %1}, %2;" : "=r"(lo), "=r"(hi) : "l"(acc))

// ---------------- scratch (device globals; no allocation allowed) ----------
__device__ int   g_flag64;                   // 1 if indices are int64
__device__ int   g_cnt[N_NODES];             // per-node in-degree (atomic cursor)
__device__ __align__(256) int    g_csr [N_NODES * STRIDE];  // 51.2MB bucketed CSR
__device__ __align__(256) float4 g_x4  [N_NODES];           // x padded to 16B rows
__device__ __align__(256) float  g_agg1[N_NODES * 4];
__device__ __align__(256) __half g_t2h [N_NODES * 16];      // h1 @ W2_rel^T (fp16)
__device__ __align__(256) float  g_r2  [N_NODES * 16];      // h1 @ W2_root^T
__device__ __align__(256) float  g_agg2[N_NODES * 16];
__device__ __align__(256) __half g_t3h [N_NODES * 8];       // h2 @ W3_rel^T (fp16)
__device__ __align__(256) float  g_r3  [N_NODES * 8];
__device__ __align__(256) float  g_agg3[N_NODES * 8];
__device__ __align__(256) float  g_pool[N_GRAPHS * 8];

// ---------------- zero + pad x + dtype probe (block 0) ---------------------
__global__ void k_zero(const float* __restrict__ x, const int* __restrict__ ei32) {
    int i = blockIdx.x * blockDim.x + threadIdx.x;
    if (i < N_NODES) {
        g_cnt[i] = 0;
        const float* xp = x + (long long)i * 3;
        g_x4[i] = make_float4(xp[0], xp[1], xp[2], 0.f);
    }
    if (i < N_GRAPHS * 8) g_pool[i] = 0.f;
    if (blockIdx.x == 0) {
        int nz = 0;
#pragma unroll
        for (int j = 0; j < 8; j++) nz += (ei32[1 + 2 * (threadIdx.x * 8 + j)] != 0);
        int total = __syncthreads_count(nz != 0);
        if (threadIdx.x == 0) g_flag64 = (total == 0) ? 1 : 0;
    }
}

// ---------------- single edge pass: bucketed CSR placement (4 edges/thread) -
__global__ void k_place(const void* __restrict__ ei) {
    int t = blockIdx.x * blockDim.x + threadIdx.x;
    int e = t * 4;                       // grid sized exactly: no bounds check
    long long s[4], d[4];
    if (g_flag64) {
        const long long* p = reinterpret_cast<const long long*>(ei);
        longlong2 a0 = *reinterpret_cast<const longlong2*>(p + e);
        longlong2 a1 = *reinterpret_cast<const longlong2*>(p + e + 2);
        longlong2 b0 = *reinterpret_cast<const longlong2*>(p + N_EDGES + e);
        longlong2 b1 = *reinterpret_cast<const longlong2*>(p + N_EDGES + e + 2);
        s[0] = a0.x; s[1] = a0.y; s[2] = a1.x; s[3] = a1.y;
        d[0] = b0.x; d[1] = b0.y; d[2] = b1.x; d[3] = b1.y;
    } else {
        const int* p = reinterpret_cast<const int*>(ei);
        int4 a = *reinterpret_cast<const int4*>(p + e);
        int4 b = *reinterpret_cast<const int4*>(p + N_EDGES + e);
        s[0] = a.x; s[1] = a.y; s[2] = a.z; s[3] = a.w;
        d[0] = b.x; d[1] = b.y; d[2] = b.z; d[3] = b.w;
    }
#pragma unroll
    for (int u = 0; u < 4; u++) {
        int p = atomicAdd(&g_cnt[d[u]], 1);
        if (p < STRIDE) g_csr[d[u] * STRIDE + p] = (int)s[u];
    }
}

// ---------------- pull aggregation, layer 1 (x4 rows, 16B) ------------------
__global__ void k_agg1() {
    int gid = blockIdx.x * blockDim.x + threadIdx.x;   // exactly N_NODES*4 threads
    int node = gid >> 2, sub = gid & 3;
    int deg = min(g_cnt[node], STRIDE);
    const int4* cp = reinterpret_cast<const int4*>(g_csr + node * STRIDE);
    float ax = 0.f, ay = 0.f, az = 0.f;
    int k4 = deg >> 2;
#pragma unroll 4
    for (int q = 0; q < k4; q++) {
        int4 s4 = __ldg(cp + q);
        int s = (sub & 1) ? ((sub & 2) ? s4.w : s4.y)
                          : ((sub & 2) ? s4.z : s4.x);
        float4 v = __ldg(&g_x4[s]);
        ax += v.x; ay += v.y; az += v.z;
    }
    int rem = deg & 3;
    if (sub < rem) {
        int s = __ldg(&g_csr[node * STRIDE + k4 * 4 + sub]);
        float4 v = __ldg(&g_x4[s]);
        ax += v.x; ay += v.y; az += v.z;
    }
    const unsigned m = 0xffffffffu;
    ax += __shfl_xor_sync(m, ax, 1); ay += __shfl_xor_sync(m, ay, 1); az += __shfl_xor_sync(m, az, 1);
    ax += __shfl_xor_sync(m, ax, 2); ay += __shfl_xor_sync(m, ay, 2); az += __shfl_xor_sync(m, az, 2);
    if (sub == 0)
        *reinterpret_cast<float4*>(g_agg1 + node * 4) = make_float4(ax, ay, az, 0.f);
}

// ---------------- pull aggregation, layer 2 (16 halfs, fp32 accum) ----------
__global__ void k_agg2() {
    int gid = blockIdx.x * blockDim.x + threadIdx.x;
    int node = gid >> 2, sub = gid & 3;
    int deg = min(g_cnt[node], STRIDE);
    int base = node * STRIDE;
    const int4* cp = reinterpret_cast<const int4*>(g_csr + base);
    const uint2* t2 = reinterpret_cast<const uint2*>(g_t2h);  // 4 halfs per uint2
    float4 acc = make_float4(0.f, 0.f, 0.f, 0.f);
    int k4 = deg >> 2;
#pragma unroll 4
    for (int q = 0; q < k4; q++) {
        int4 s = __ldg(cp + q);
        uint2 a = __ldg(t2 + (size_t)s.x * 4 + sub);
        uint2 b = __ldg(t2 + (size_t)s.y * 4 + sub);
        uint2 c = __ldg(t2 + (size_t)s.z * 4 + sub);
        uint2 d = __ldg(t2 + (size_t)s.w * 4 + sub);
#pragma unroll
        for (int r = 0; r < 4; r++) {
            uint2 v = (r == 0) ? a : (r == 1) ? b : (r == 2) ? c : d;
            float2 f0 = __half22float2(*reinterpret_cast<__half2*>(&v.x));
            float2 f1 = __half22float2(*reinterpret_cast<__half2*>(&v.y));
            acc.x += f0.x; acc.y += f0.y; acc.z += f1.x; acc.w += f1.y;
        }
    }
    for (int k = k4 * 4; k < deg; k++) {
        int s = __ldg(&g_csr[base + k]);
        uint2 v = __ldg(t2 + (size_t)s * 4 + sub);
        float2 f0 = __half22float2(*reinterpret_cast<__half2*>(&v.x));
        float2 f1 = __half22float2(*reinterpret_cast<__half2*>(&v.y));
        acc.x += f0.x; acc.y += f0.y; acc.z += f1.x; acc.w += f1.y;
    }
    reinterpret_cast<float4*>(g_agg2)[(size_t)node * 4 + sub] = acc;
}

// ---------------- pull aggregation, layer 3 (8 halfs, fp32 accum) -----------
__global__ void k_agg3() {
    int gid = blockIdx.x * blockDim.x + threadIdx.x;
    int node = gid >> 2, sub = gid & 3;
    int deg = min(g_cnt[node], STRIDE);
    int base = node * STRIDE;
    const int4* cp = reinterpret_cast<const int4*>(g_csr + base);
    const unsigned* t3 = reinterpret_cast<const unsigned*>(g_t3h);  // 2 halfs per uint
    float2 acc = make_float2(0.f, 0.f);
    int k4 = deg >> 2;
#pragma unroll 4
    for (int q = 0; q < k4; q++) {
        int4 s = __ldg(cp + q);
        unsigned a = __ldg(t3 + (size_t)s.x * 4 + sub);
        unsigned b = __ldg(t3 + (size_t)s.y * 4 + sub);
        unsigned c = __ldg(t3 + (size_t)s.z * 4 + sub);
        unsigned d = __ldg(t3 + (size_t)s.w * 4 + sub);
        float2 fa = __half22float2(*reinterpret_cast<__half2*>(&a));
        float2 fb = __half22float2(*reinterpret_cast<__half2*>(&b));
        float2 fc = __half22float2(*reinterpret_cast<__half2*>(&c));
        float2 fd = __half22float2(*reinterpret_cast<__half2*>(&d));
        acc.x += (fa.x + fb.x) + (fc.x + fd.x);
        acc.y += (fa.y + fb.y) + (fc.y + fd.y);
    }
    for (int k = k4 * 4; k < deg; k++) {
        int s = __ldg(&g_csr[base + k]);
        unsigned v = __ldg(t3 + (size_t)s * 4 + sub);
        float2 f = __half22float2(*reinterpret_cast<__half2*>(&v));
        acc.x += f.x; acc.y += f.y;
    }
    reinterpret_cast<float2*>(g_agg3)[(size_t)node * 4 + sub] = acc;
}

// ---------------- node pass 1: h1 = relu(...); t2/r2 = h1 @ W2^T ------------
// ONE thread per node, broadcast weight LDS (96 regs, pareto-optimal).
__global__ void k_node1(const float* __restrict__ W1_rel, const float* __restrict__ b1,
                        const float* __restrict__ W1_root,
                        const float* __restrict__ W2_rel, const float* __restrict__ W2_root) {
    __shared__ float4 s1rel[32];    // (w0,w1,w2,bias)
    __shared__ float4 s1root[32];   // (w0,w1,w2,0)
    __shared__ float4 s2rel[128];   // 16x32 natural row-major
    __shared__ float4 s2root[128];
    if (threadIdx.x < 32) {
        int o = threadIdx.x;
        s1rel[o]  = make_float4(W1_rel[o * 3], W1_rel[o * 3 + 1], W1_rel[o * 3 + 2], b1[o]);
        s1root[o] = make_float4(W1_root[o * 3], W1_root[o * 3 + 1], W1_root[o * 3 + 2], 0.f);
    }
    for (int j = threadIdx.x; j < 128; j += blockDim.x) {
        s2rel[j]  = reinterpret_cast<const float4*>(W2_rel)[j];
        s2root[j] = reinterpret_cast<const float4*>(W2_root)[j];
    }
    __syncthreads();

    int i = blockIdx.x * blockDim.x + threadIdx.x;
    if (i >= N_NODES) return;

    float4 a  = *reinterpret_cast<const float4*>(g_agg1 + i * 4);
    float4 xv = __ldg(&g_x4[i]);

    // h1 packed as consecutive-k pairs: hh[kk] = {h[2kk], h[2kk+1]}
    unsigned long long hh[16];
#pragma unroll
    for (int kk = 0; kk < 16; kk++) {
        unsigned u[2];
#pragma unroll
        for (int half = 0; half < 2; half++) {
            int o = kk * 2 + half;
            float4 wa = s1rel[o];
            float4 wr = s1root[o];
            float v = wa.w;
            v = fmaf(wa.x, a.x, v);  v = fmaf(wa.y, a.y, v);  v = fmaf(wa.z, a.z, v);
            v = fmaf(wr.x, xv.x, v); v = fmaf(wr.y, xv.y, v); v = fmaf(wr.z, xv.z, v);
            u[half] = __float_as_uint(fmaxf(v, 0.f));
        }
        asm("mov.b64 %0, {%1, %2};" : "=l"(hh[kk]) : "r"(u[0]), "r"(u[1]));
    }

    const ulonglong2* wrel  = reinterpret_cast<const ulonglong2*>(s2rel);
    const ulonglong2* wroot = reinterpret_cast<const ulonglong2*>(s2root);

    // t2 outputs: 16 rows (fp16)
    __half2 hp[8];
#pragma unroll
    for (int p = 0; p < 8; p++) {
        float res[2];
#pragma unroll
        for (int half = 0; half < 2; half++) {
            int o = p * 2 + half;
            unsigned long long acc = 0ULL;
#pragma unroll
            for (int c = 0; c < 8; c++) {           // c = 4-k chunk
                ulonglong2 w = wrel[o * 8 + c];
                FMA2(acc, w.x, hh[c * 2]);
                FMA2(acc, w.y, hh[c * 2 + 1]);
            }
            unsigned lo, hi; UNPACK2(lo, hi, acc);
            res[half] = __uint_as_float(lo) + __uint_as_float(hi);
        }
        hp[p] = __floats2half2_rn(res[0], res[1]);
    }
    uint4* tp = reinterpret_cast<uint4*>(g_t2h + (size_t)i * 16);
    tp[0] = *reinterpret_cast<uint4*>(hp);
    tp[1] = *reinterpret_cast<uint4*>(hp + 4);

    // r2 outputs: 16 rows (fp32)
    float rv[16];
#pragma unroll
    for (int o = 0; o < 16; o++) {
        unsigned long long acc = 0ULL;
#pragma unroll
        for (int c = 0; c < 8; c++) {
            ulonglong2 w = wroot[o * 8 + c];
            FMA2(acc, w.x, hh[c * 2]);
            FMA2(acc, w.y, hh[c * 2 + 1]);
        }
        unsigned lo, hi; UNPACK2(lo, hi, acc);
        rv[o] = __uint_as_float(lo) + __uint_as_float(hi);
    }
    float4* rp = reinterpret_cast<float4*>(g_r2 + (size_t)i * 16);
#pragma unroll
    for (int q = 0; q < 4; q++)
        rp[q] = make_float4(rv[q * 4], rv[q * 4 + 1], rv[q * 4 + 2], rv[q * 4 + 3]);
}

// ---------------- node pass 2: h2 = relu(agg2 + r2 + b2); t3(fp16)/r3 -------
__global__ void k_node2(const float* __restrict__ b2,
                        const float* __restrict__ W3_rel, const float* __restrict__ W3_root) {
    __shared__ float4 sb2[4];
    __shared__ float4 s3rel[32];    // 8 rows x 4 float4
    __shared__ float4 s3root[32];
    if (threadIdx.x < 4)  sb2[threadIdx.x] = reinterpret_cast<const float4*>(b2)[threadIdx.x];
    if (threadIdx.x >= 32 && threadIdx.x < 64)
        s3rel[threadIdx.x - 32] = reinterpret_cast<const float4*>(W3_rel)[threadIdx.x - 32];
    if (threadIdx.x >= 64 && threadIdx.x < 96)
        s3root[threadIdx.x - 64] = reinterpret_cast<const float4*>(W3_root)[threadIdx.x - 64];
    __syncthreads();

    int i = blockIdx.x * blockDim.x + threadIdx.x;
    if (i >= N_NODES) return;

    float h[16];
    const float4* ap = reinterpret_cast<const float4*>(g_agg2 + i * 16);
    const float4* rp = reinterpret_cast<const float4*>(g_r2 + i * 16);
#pragma unroll
    for (int q = 0; q < 4; q++) {
        float4 av = ap[q];
        float4 rv = rp[q];
        float4 bv = sb2[q];
        h[q * 4 + 0] = fmaxf(av.x + rv.x + bv.x, 0.f);
        h[q * 4 + 1] = fmaxf(av.y + rv.y + bv.y, 0.f);
        h[q * 4 + 2] = fmaxf(av.z + rv.z + bv.z, 0.f);
        h[q * 4 + 3] = fmaxf(av.w + rv.w + bv.w, 0.f);
    }

    float tv[8], rv2[8];
#pragma unroll
    for (int o = 0; o < 8; o++) {
        float tt = 0.f, rr = 0.f;
#pragma unroll
        for (int k = 0; k < 4; k++) {
            float4 wt = s3rel[o * 4 + k];
            float4 wr = s3root[o * 4 + k];
            tt = fmaf(h[k * 4 + 0], wt.x, tt); tt = fmaf(h[k * 4 + 1], wt.y, tt);
            tt = fmaf(h[k * 4 + 2], wt.z, tt); tt = fmaf(h[k * 4 + 3], wt.w, tt);
            rr = fmaf(h[k * 4 + 0], wr.x, rr); rr = fmaf(h[k * 4 + 1], wr.y, rr);
            rr = fmaf(h[k * 4 + 2], wr.z, rr); rr = fmaf(h[k * 4 + 3], wr.w, rr);
        }
        tv[o] = tt; rv2[o] = rr;
    }
    __half2 hp[4];
#pragma unroll
    for (int q = 0; q < 4; q++) hp[q] = __floats2half2_rn(tv[q * 2], tv[q * 2 + 1]);
    *reinterpret_cast<uint4*>(g_t3h + i * 8) = *reinterpret_cast<uint4*>(hp);

    float4* r3p = reinterpret_cast<float4*>(g_r3 + i * 8);
    r3p[0] = make_float4(rv2[0], rv2[1], rv2[2], rv2[3]);
    r3p[1] = make_float4(rv2[4], rv2[5], rv2[6], rv2[7]);
}

// ---------------- node pass 3: h3 = relu(agg3 + r3 + b3); segment max -------
__global__ void k_node3(const void* __restrict__ batch,
                        const float* __restrict__ b3) {
    int i = blockIdx.x * blockDim.x + threadIdx.x;
    if (i >= N_NODES) i = N_NODES - 1;  // duplicates harmless under max
    int lane = threadIdx.x & 31;

    float h[8];
    const float4* ap = reinterpret_cast<const float4*>(g_agg3 + i * 8);
    const float4* rp = reinterpret_cast<const float4*>(g_r3 + i * 8);
#pragma unroll
    for (int q = 0; q < 2; q++) {
        float4 av = ap[q];
        float4 rv = rp[q];
        h[q * 4 + 0] = fmaxf(av.x + rv.x + __ldg(b3 + q * 4 + 0), 0.f);
        h[q * 4 + 1] = fmaxf(av.y + rv.y + __ldg(b3 + q * 4 + 1), 0.f);
        h[q * 4 + 2] = fmaxf(av.z + rv.z + __ldg(b3 + q * 4 + 2), 0.f);
        h[q * 4 + 3] = fmaxf(av.w + rv.w + __ldg(b3 + q * 4 + 3), 0.f);
    }
    int b;
    if (g_flag64) b = (int)reinterpret_cast<const long long*>(batch)[i];
    else          b = reinterpret_cast<const int*>(batch)[i];

    const unsigned m = 0xffffffffu;
#pragma unroll
    for (int off = 1; off < 32; off <<= 1) {
        int ob = __shfl_down_sync(m, b, off);
#pragma unroll
        for (int d = 0; d < 8; d++) {
            float oh = __shfl_down_sync(m, h[d], off);
            if (ob == b) h[d] = fmaxf(h[d], oh);
        }
    }
    int pb = __shfl_up_sync(m, b, 1);
    bool leader = (lane == 0) || (pb != b);
    if (leader) {
#pragma unroll
        for (int d = 0; d < 8; d++)
            atomicMax(reinterpret_cast<int*>(&g_pool[b * 8 + d]), __float_as_int(h[d]));
    }
}

// ---------------- final: out[g] = pooled[g] . W_lin + b_lin -----------------
__global__ void k_final(const float* __restrict__ W_lin, const float* __restrict__ b_lin,
                        float* __restrict__ out) {
    int g = blockIdx.x * blockDim.x + threadIdx.x;
    if (g >= N_GRAPHS) return;
    float acc = __ldg(b_lin);
#pragma unroll
    for (int d = 0; d < 8; d++) acc += g_pool[g * 8 + d] * __ldg(W_lin + d);
    out[g] = acc;
}

// ---------------- launch ----------------------------------------------------
extern "C" void kernel_launch(void* const* d_in, const int* in_sizes, int n_in,
                              void* d_out, int out_size) {
    const float* x      = (const float*)d_in[0];
    const void*  ei     = d_in[1];
    const void*  batch  = d_in[2];
    const float* W1_rel = (const float*)d_in[3];
    const float* b1     = (const float*)d_in[4];
    const float* W1_root= (const float*)d_in[5];
    const float* W2_rel = (const float*)d_in[6];
    const float* b2     = (const float*)d_in[7];
    const float* W2_root= (const float*)d_in[8];
    const float* W3_rel = (const float*)d_in[9];
    const float* b3     = (const float*)d_in[10];
    const float* W3_root= (const float*)d_in[11];
    const float* W_lin  = (const float*)d_in[12];
    const float* b_lin  = (const float*)d_in[13];
    float* out = (float*)d_out;

    const int PLACE_BLOCKS = N_EDGES / 4 / 256;         // 6250 exact
    const int AGG_BLOCKS   = (N_NODES * 4) / 256;       // 3125 exact
    const int NODE_BLOCKS  = (N_NODES + 255) / 256;     // 782

    k_zero<<<NODE_BLOCKS, 256>>>(x, (const int*)ei);
    k_place<<<PLACE_BLOCKS, 256>>>(ei);
    k_agg1<<<AGG_BLOCKS, 256>>>();
    k_node1<<<NODE_BLOCKS, 256>>>(W1_rel, b1, W1_root, W2_rel, W2_root);
    k_agg2<<<AGG_BLOCKS, 256>>>();
    k_node2<<<NODE_BLOCKS, 256>>>(b2, W3_rel, W3_root);
    k_agg3<<<AGG_BLOCKS, 256>>>();
    k_node3<<<NODE_BLOCKS, 256>>>(batch, b3);
    k_final<<<2, 256>>>(W_lin, b_lin, out);
}

// round 17
// speedup vs baseline: 1.0844x; 1.0157x over previous
#include <cuda_runtime.h>
#include <cuda_fp16.h>

#define N_NODES  200000
#define N_EDGES  6400000
#define N_GRAPHS 512
#define STRIDE   64          // CSR bucket capacity (mean deg 32, sigma 5.7; 5.7σ tail safe)
#define NPB      64          // nodes per block in fused layer3

// Packed dual fp32 FMA (sm_103a): acc = w * h + acc on both lanes.
#define FMA2(acc, w, hh) \
    asm("fma.rn.f32x2 %0, %1, %2, %0;" : "+l"(acc) : "l"(w), "l"(hh))
#define UNPACK2(lo, hi, acc) \
    asm("mov.b64 {%0, %1}, %2;" : "=r"(lo), "=r"(hi) : "l"(acc))

// ---------------- scratch (device globals; no allocation allowed) ----------
__device__ int   g_flag64;                   // 1 if indices are int64
__device__ int   g_cnt[N_NODES];             // per-node in-degree (atomic cursor)
__device__ __align__(256) int    g_csr [N_NODES * STRIDE];  // 51.2MB bucketed CSR
__device__ __align__(256) float4 g_x4  [N_NODES];           // x padded to 16B rows
__device__ __align__(256) float  g_agg1[N_NODES * 4];
__device__ __align__(256) __half g_t2h [N_NODES * 16];      // h1 @ W2_rel^T (fp16)
__device__ __align__(256) float  g_r2  [N_NODES * 16];      // h1 @ W2_root^T
__device__ __align__(256) float  g_agg2[N_NODES * 16];
__device__ __align__(256) __half g_t3h [N_NODES * 8];       // h2 @ W3_rel^T (fp16)
__device__ __align__(256) float  g_r3  [N_NODES * 8];
__device__ __align__(256) float  g_pool[N_GRAPHS * 8];

// ---------------- zero + pad x + dtype probe (block 0) ---------------------
__global__ void k_zero(const float* __restrict__ x, const int* __restrict__ ei32) {
    int i = blockIdx.x * blockDim.x + threadIdx.x;
    if (i < N_NODES) {
        g_cnt[i] = 0;
        const float* xp = x + (long long)i * 3;
        g_x4[i] = make_float4(xp[0], xp[1], xp[2], 0.f);
    }
    if (i < N_GRAPHS * 8) g_pool[i] = 0.f;
    if (blockIdx.x == 0) {
        int nz = 0;
#pragma unroll
        for (int j = 0; j < 8; j++) nz += (ei32[1 + 2 * (threadIdx.x * 8 + j)] != 0);
        int total = __syncthreads_count(nz != 0);
        if (threadIdx.x == 0) g_flag64 = (total == 0) ? 1 : 0;
    }
}

// ---------------- single edge pass: bucketed CSR placement (4 edges/thread) -
__global__ void k_place(const void* __restrict__ ei) {
    int t = blockIdx.x * blockDim.x + threadIdx.x;
    int e = t * 4;                       // grid sized exactly: no bounds check
    long long s[4], d[4];
    if (g_flag64) {
        const long long* p = reinterpret_cast<const long long*>(ei);
        longlong2 a0 = *reinterpret_cast<const longlong2*>(p + e);
        longlong2 a1 = *reinterpret_cast<const longlong2*>(p + e + 2);
        longlong2 b0 = *reinterpret_cast<const longlong2*>(p + N_EDGES + e);
        longlong2 b1 = *reinterpret_cast<const longlong2*>(p + N_EDGES + e + 2);
        s[0] = a0.x; s[1] = a0.y; s[2] = a1.x; s[3] = a1.y;
        d[0] = b0.x; d[1] = b0.y; d[2] = b1.x; d[3] = b1.y;
    } else {
        const int* p = reinterpret_cast<const int*>(ei);
        int4 a = *reinterpret_cast<const int4*>(p + e);
        int4 b = *reinterpret_cast<const int4*>(p + N_EDGES + e);
        s[0] = a.x; s[1] = a.y; s[2] = a.z; s[3] = a.w;
        d[0] = b.x; d[1] = b.y; d[2] = b.z; d[3] = b.w;
    }
#pragma unroll
    for (int u = 0; u < 4; u++) {
        int p = atomicAdd(&g_cnt[d[u]], 1);
        if (p < STRIDE) g_csr[d[u] * STRIDE + p] = (int)s[u];
    }
}

// ---------------- pull aggregation, layer 1 (x4 rows, 16B) ------------------
__global__ void k_agg1() {
    int gid = blockIdx.x * blockDim.x + threadIdx.x;   // exactly N_NODES*4 threads
    int node = gid >> 2, sub = gid & 3;
    int deg = min(g_cnt[node], STRIDE);
    const int4* cp = reinterpret_cast<const int4*>(g_csr + node * STRIDE);
    float ax = 0.f, ay = 0.f, az = 0.f;
    int k4 = deg >> 2;
#pragma unroll 4
    for (int q = 0; q < k4; q++) {
        int4 s4 = __ldg(cp + q);
        int s = (sub & 1) ? ((sub & 2) ? s4.w : s4.y)
                          : ((sub & 2) ? s4.z : s4.x);
        float4 v = __ldg(&g_x4[s]);
        ax += v.x; ay += v.y; az += v.z;
    }
    int rem = deg & 3;
    if (sub < rem) {
        int s = __ldg(&g_csr[node * STRIDE + k4 * 4 + sub]);
        float4 v = __ldg(&g_x4[s]);
        ax += v.x; ay += v.y; az += v.z;
    }
    const unsigned m = 0xffffffffu;
    ax += __shfl_xor_sync(m, ax, 1); ay += __shfl_xor_sync(m, ay, 1); az += __shfl_xor_sync(m, az, 1);
    ax += __shfl_xor_sync(m, ax, 2); ay += __shfl_xor_sync(m, ay, 2); az += __shfl_xor_sync(m, az, 2);
    if (sub == 0)
        *reinterpret_cast<float4*>(g_agg1 + node * 4) = make_float4(ax, ay, az, 0.f);
}

// ---------------- pull aggregation, layer 2 (16 halfs, fp32 accum) ----------
__global__ void k_agg2() {
    int gid = blockIdx.x * blockDim.x + threadIdx.x;
    int node = gid >> 2, sub = gid & 3;
    int deg = min(g_cnt[node], STRIDE);
    int base = node * STRIDE;
    const int4* cp = reinterpret_cast<const int4*>(g_csr + base);
    const uint2* t2 = reinterpret_cast<const uint2*>(g_t2h);  // 4 halfs per uint2
    float4 acc = make_float4(0.f, 0.f, 0.f, 0.f);
    int k4 = deg >> 2;
#pragma unroll 4
    for (int q = 0; q < k4; q++) {
        int4 s = __ldg(cp + q);
        uint2 a = __ldg(t2 + (size_t)s.x * 4 + sub);
        uint2 b = __ldg(t2 + (size_t)s.y * 4 + sub);
        uint2 c = __ldg(t2 + (size_t)s.z * 4 + sub);
        uint2 d = __ldg(t2 + (size_t)s.w * 4 + sub);
#pragma unroll
        for (int r = 0; r < 4; r++) {
            uint2 v = (r == 0) ? a : (r == 1) ? b : (r == 2) ? c : d;
            float2 f0 = __half22float2(*reinterpret_cast<__half2*>(&v.x));
            float2 f1 = __half22float2(*reinterpret_cast<__half2*>(&v.y));
            acc.x += f0.x; acc.y += f0.y; acc.z += f1.x; acc.w += f1.y;
        }
    }
    for (int k = k4 * 4; k < deg; k++) {
        int s = __ldg(&g_csr[base + k]);
        uint2 v = __ldg(t2 + (size_t)s * 4 + sub);
        float2 f0 = __half22float2(*reinterpret_cast<__half2*>(&v.x));
        float2 f1 = __half22float2(*reinterpret_cast<__half2*>(&v.y));
        acc.x += f0.x; acc.y += f0.y; acc.z += f1.x; acc.w += f1.y;
    }
    reinterpret_cast<float4*>(g_agg2)[(size_t)node * 4 + sub] = acc;
}

// ---------------- node pass 1: h1 = relu(...); t2/r2 = h1 @ W2^T ------------
// ONE thread per node, broadcast weight LDS (96 regs, pareto-optimal).
__global__ void k_node1(const float* __restrict__ W1_rel, const float* __restrict__ b1,
                        const float* __restrict__ W1_root,
                        const float* __restrict__ W2_rel, const float* __restrict__ W2_root) {
    __shared__ float4 s1rel[32];    // (w0,w1,w2,bias)
    __shared__ float4 s1root[32];   // (w0,w1,w2,0)
    __shared__ float4 s2rel[128];   // 16x32 natural row-major
    __shared__ float4 s2root[128];
    if (threadIdx.x < 32) {
        int o = threadIdx.x;
        s1rel[o]  = make_float4(W1_rel[o * 3], W1_rel[o * 3 + 1], W1_rel[o * 3 + 2], b1[o]);
        s1root[o] = make_float4(W1_root[o * 3], W1_root[o * 3 + 1], W1_root[o * 3 + 2], 0.f);
    }
    for (int j = threadIdx.x; j < 128; j += blockDim.x) {
        s2rel[j]  = reinterpret_cast<const float4*>(W2_rel)[j];
        s2root[j] = reinterpret_cast<const float4*>(W2_root)[j];
    }
    __syncthreads();

    int i = blockIdx.x * blockDim.x + threadIdx.x;
    if (i >= N_NODES) return;

    float4 a  = *reinterpret_cast<const float4*>(g_agg1 + i * 4);
    float4 xv = __ldg(&g_x4[i]);

    // h1 packed as consecutive-k pairs: hh[kk] = {h[2kk], h[2kk+1]}
    unsigned long long hh[16];
#pragma unroll
    for (int kk = 0; kk < 16; kk++) {
        unsigned u[2];
#pragma unroll
        for (int half = 0; half < 2; half++) {
            int o = kk * 2 + half;
            float4 wa = s1rel[o];
            float4 wr = s1root[o];
            float v = wa.w;
            v = fmaf(wa.x, a.x, v);  v = fmaf(wa.y, a.y, v);  v = fmaf(wa.z, a.z, v);
            v = fmaf(wr.x, xv.x, v); v = fmaf(wr.y, xv.y, v); v = fmaf(wr.z, xv.z, v);
            u[half] = __float_as_uint(fmaxf(v, 0.f));
        }
        asm("mov.b64 %0, {%1, %2};" : "=l"(hh[kk]) : "r"(u[0]), "r"(u[1]));
    }

    const ulonglong2* wrel  = reinterpret_cast<const ulonglong2*>(s2rel);
    const ulonglong2* wroot = reinterpret_cast<const ulonglong2*>(s2root);

    // t2 outputs: 16 rows (fp16)
    __half2 hp[8];
#pragma unroll
    for (int p = 0; p < 8; p++) {
        float res[2];
#pragma unroll
        for (int half = 0; half < 2; half++) {
            int o = p * 2 + half;
            unsigned long long acc = 0ULL;
#pragma unroll
            for (int c = 0; c < 8; c++) {           // c = 4-k chunk
                ulonglong2 w = wrel[o * 8 + c];
                FMA2(acc, w.x, hh[c * 2]);
                FMA2(acc, w.y, hh[c * 2 + 1]);
            }
            unsigned lo, hi; UNPACK2(lo, hi, acc);
            res[half] = __uint_as_float(lo) + __uint_as_float(hi);
        }
        hp[p] = __floats2half2_rn(res[0], res[1]);
    }
    uint4* tp = reinterpret_cast<uint4*>(g_t2h + (size_t)i * 16);
    tp[0] = *reinterpret_cast<uint4*>(hp);
    tp[1] = *reinterpret_cast<uint4*>(hp + 4);

    // r2 outputs: 16 rows (fp32)
    float rv[16];
#pragma unroll
    for (int o = 0; o < 16; o++) {
        unsigned long long acc = 0ULL;
#pragma unroll
        for (int c = 0; c < 8; c++) {
            ulonglong2 w = wroot[o * 8 + c];
            FMA2(acc, w.x, hh[c * 2]);
            FMA2(acc, w.y, hh[c * 2 + 1]);
        }
        unsigned lo, hi; UNPACK2(lo, hi, acc);
        rv[o] = __uint_as_float(lo) + __uint_as_float(hi);
    }
    float4* rp = reinterpret_cast<float4*>(g_r2 + (size_t)i * 16);
#pragma unroll
    for (int q = 0; q < 4; q++)
        rp[q] = make_float4(rv[q * 4], rv[q * 4 + 1], rv[q * 4 + 2], rv[q * 4 + 3]);
}

// ---------------- node pass 2: h2 = relu(agg2 + r2 + b2); t3(fp16)/r3 -------
__global__ void k_node2(const float* __restrict__ b2,
                        const float* __restrict__ W3_rel, const float* __restrict__ W3_root) {
    __shared__ float4 sb2[4];
    __shared__ float4 s3rel[32];    // 8 rows x 4 float4
    __shared__ float4 s3root[32];
    if (threadIdx.x < 4)  sb2[threadIdx.x] = reinterpret_cast<const float4*>(b2)[threadIdx.x];
    if (threadIdx.x >= 32 && threadIdx.x < 64)
        s3rel[threadIdx.x - 32] = reinterpret_cast<const float4*>(W3_rel)[threadIdx.x - 32];
    if (threadIdx.x >= 64 && threadIdx.x < 96)
        s3root[threadIdx.x - 64] = reinterpret_cast<const float4*>(W3_root)[threadIdx.x - 64];
    __syncthreads();

    int i = blockIdx.x * blockDim.x + threadIdx.x;
    if (i >= N_NODES) return;

    float h[16];
    const float4* ap = reinterpret_cast<const float4*>(g_agg2 + i * 16);
    const float4* rp = reinterpret_cast<const float4*>(g_r2 + i * 16);
#pragma unroll
    for (int q = 0; q < 4; q++) {
        float4 av = ap[q];
        float4 rv = rp[q];
        float4 bv = sb2[q];
        h[q * 4 + 0] = fmaxf(av.x + rv.x + bv.x, 0.f);
        h[q * 4 + 1] = fmaxf(av.y + rv.y + bv.y, 0.f);
        h[q * 4 + 2] = fmaxf(av.z + rv.z + bv.z, 0.f);
        h[q * 4 + 3] = fmaxf(av.w + rv.w + bv.w, 0.f);
    }

    float tv[8], rv2[8];
#pragma unroll
    for (int o = 0; o < 8; o++) {
        float tt = 0.f, rr = 0.f;
#pragma unroll
        for (int k = 0; k < 4; k++) {
            float4 wt = s3rel[o * 4 + k];
            float4 wr = s3root[o * 4 + k];
            tt = fmaf(h[k * 4 + 0], wt.x, tt); tt = fmaf(h[k * 4 + 1], wt.y, tt);
            tt = fmaf(h[k * 4 + 2], wt.z, tt); tt = fmaf(h[k * 4 + 3], wt.w, tt);
            rr = fmaf(h[k * 4 + 0], wr.x, rr); rr = fmaf(h[k * 4 + 1], wr.y, rr);
            rr = fmaf(h[k * 4 + 2], wr.z, rr); rr = fmaf(h[k * 4 + 3], wr.w, rr);
        }
        tv[o] = tt; rv2[o] = rr;
    }
    __half2 hp[4];
#pragma unroll
    for (int q = 0; q < 4; q++) hp[q] = __floats2half2_rn(tv[q * 2], tv[q * 2 + 1]);
    *reinterpret_cast<uint4*>(g_t3h + i * 8) = *reinterpret_cast<uint4*>(hp);

    float4* r3p = reinterpret_cast<float4*>(g_r3 + i * 8);
    r3p[0] = make_float4(rv2[0], rv2[1], rv2[2], rv2[3]);
    r3p[1] = make_float4(rv2[4], rv2[5], rv2[6], rv2[7]);
}

// ======== fused layer 3: gather t3h -> smem -> h3 -> segment max pool =======
// Block = 64 nodes. Phase A: 256 threads gather (4/node) into smem.
// Phase B (threads 0..63): relu + butterfly-free h3 assembly + warp pool.
__global__ void __launch_bounds__(256) k_layer3(
        const void* __restrict__ batch, const float* __restrict__ b3) {
    __shared__ float2 sAcc[NPB * 4];

    // ---- Phase A: gather ----
    {
        int nl = threadIdx.x >> 2, sub = threadIdx.x & 3;
        int node = blockIdx.x * NPB + nl;
        int deg = min(g_cnt[node], STRIDE);
        int base = node * STRIDE;
        const int4* cp = reinterpret_cast<const int4*>(g_csr + base);
        const unsigned* t3 = reinterpret_cast<const unsigned*>(g_t3h);
        float2 acc = make_float2(0.f, 0.f);
        int k4 = deg >> 2;
#pragma unroll 4
        for (int q = 0; q < k4; q++) {
            int4 s = __ldg(cp + q);
            unsigned a = __ldg(t3 + (size_t)s.x * 4 + sub);
            unsigned b = __ldg(t3 + (size_t)s.y * 4 + sub);
            unsigned c = __ldg(t3 + (size_t)s.z * 4 + sub);
            unsigned d = __ldg(t3 + (size_t)s.w * 4 + sub);
            float2 fa = __half22float2(*reinterpret_cast<__half2*>(&a));
            float2 fb = __half22float2(*reinterpret_cast<__half2*>(&b));
            float2 fc = __half22float2(*reinterpret_cast<__half2*>(&c));
            float2 fd = __half22float2(*reinterpret_cast<__half2*>(&d));
            acc.x += (fa.x + fb.x) + (fc.x + fd.x);
            acc.y += (fa.y + fb.y) + (fc.y + fd.y);
        }
        for (int k = k4 * 4; k < deg; k++) {
            int s = __ldg(&g_csr[base + k]);
            unsigned v = __ldg(t3 + (size_t)s * 4 + sub);
            float2 f = __half22float2(*reinterpret_cast<__half2*>(&v));
            acc.x += f.x; acc.y += f.y;
        }
        sAcc[nl * 4 + sub] = acc;
    }
    __syncthreads();

    // ---- Phase B: h3 + segment-max pool (threads 0..63) ----
    int t = threadIdx.x;
    if (t >= 64) return;
    int i = blockIdx.x * NPB + t;
    int lane = t & 31;

    const float2* rp = reinterpret_cast<const float2*>(g_r3 + (size_t)i * 8);
    float h[8];
#pragma unroll
    for (int q = 0; q < 4; q++) {
        float2 av = sAcc[t * 4 + q];
        float2 rv = rp[q];
        h[q * 2 + 0] = fmaxf(av.x + rv.x + __ldg(b3 + q * 2 + 0), 0.f);
        h[q * 2 + 1] = fmaxf(av.y + rv.y + __ldg(b3 + q * 2 + 1), 0.f);
    }
    int b;
    if (g_flag64) b = (int)reinterpret_cast<const long long*>(batch)[i];
    else          b = reinterpret_cast<const int*>(batch)[i];

    const unsigned m = 0xffffffffu;
#pragma unroll
    for (int off = 1; off < 32; off <<= 1) {
        int ob = __shfl_down_sync(m, b, off);
#pragma unroll
        for (int d = 0; d < 8; d++) {
            float oh = __shfl_down_sync(m, h[d], off);
            if (ob == b) h[d] = fmaxf(h[d], oh);
        }
    }
    int pb = __shfl_up_sync(m, b, 1);
    bool leader = (lane == 0) || (pb != b);
    if (leader) {
#pragma unroll
        for (int d = 0; d < 8; d++)
            atomicMax(reinterpret_cast<int*>(&g_pool[b * 8 + d]), __float_as_int(h[d]));
    }
}

// ---------------- final: out[g] = pooled[g] . W_lin + b_lin -----------------
__global__ void k_final(const float* __restrict__ W_lin, const float* __restrict__ b_lin,
                        float* __restrict__ out) {
    int g = blockIdx.x * blockDim.x + threadIdx.x;
    if (g >= N_GRAPHS) return;
    float acc = __ldg(b_lin);
#pragma unroll
    for (int d = 0; d < 8; d++) acc += g_pool[g * 8 + d] * __ldg(W_lin + d);
    out[g] = acc;
}

// ---------------- launch ----------------------------------------------------
extern "C" void kernel_launch(void* const* d_in, const int* in_sizes, int n_in,
                              void* d_out, int out_size) {
    const float* x      = (const float*)d_in[0];
    const void*  ei     = d_in[1];
    const void*  batch  = d_in[2];
    const float* W1_rel = (const float*)d_in[3];
    const float* b1     = (const float*)d_in[4];
    const float* W1_root= (const float*)d_in[5];
    const float* W2_rel = (const float*)d_in[6];
    const float* b2     = (const float*)d_in[7];
    const float* W2_root= (const float*)d_in[8];
    const float* W3_rel = (const float*)d_in[9];
    const float* b3     = (const float*)d_in[10];
    const float* W3_root= (const float*)d_in[11];
    const float* W_lin  = (const float*)d_in[12];
    const float* b_lin  = (const float*)d_in[13];
    float* out = (float*)d_out;

    const int PLACE_BLOCKS = N_EDGES / 4 / 256;         // 6250 exact
    const int AGG_BLOCKS   = (N_NODES * 4) / 256;       // 3125 exact
    const int NODE_BLOCKS  = (N_NODES + 255) / 256;     // 782
    const int L3_BLOCKS    = N_NODES / NPB;             // 3125 exact

    k_zero<<<NODE_BLOCKS, 256>>>(x, (const int*)ei);
    k_place<<<PLACE_BLOCKS, 256>>>(ei);
    k_agg1<<<AGG_BLOCKS, 256>>>();
    k_node1<<<NODE_BLOCKS, 256>>>(W1_rel, b1, W1_root, W2_rel, W2_root);
    k_agg2<<<AGG_BLOCKS, 256>>>();
    k_node2<<<NODE_BLOCKS, 256>>>(b2, W3_rel, W3_root);
    k_layer3<<<L3_BLOCKS, 256>>>(batch, b3);
    k_final<<<2, 256>>>(W_lin, b_lin, out);
}